// round 1
// baseline (speedup 1.0000x reference)
#include <cuda_runtime.h>
#include <math.h>

// ---------------- problem constants ----------------
#define NT        65536      // B*T tokens
#define NBLKA     512
#define BLK_TOK   128
#define ST        32
#define NSUB      (BLK_TOK/ST)

#define O1 4194304           // w_qkv_new offset in d_out
#define O2 4243456           // w_swiglu_new offset
#define O3 4276224           // w_out_new offset

// smem strides (floats)
#define SWT_S 132            // swT[256][132]  (w_swiglu transposed)
#define SY_S  260            // sy [32][260]
#define SO_S  68             // so [64][68]    (w_out)
#define SUV_S 132            // suv[32][132]
#define SH_S  68             // sh [32][68]

#define SWT_SZ (256*SWT_S)
#define SY_SZ  (32*SY_S)
#define SO_SZ  (64*SO_S)
#define SUV_SZ (32*SUV_S)
#define SH_SZ  (32*SH_S)
#define SMEM_A_BYTES ((SWT_SZ+SY_SZ+SO_SZ+SUV_SZ+SH_SZ)*4)

// ---------------- device scratch (no allocations allowed) ----------------
__device__ float  g_aoPart[NBLKA * 4096];
__device__ float  g_ao[4096];
__device__ float2 g_rowstats[1344];
__device__ float  g_scale[3];

__device__ __forceinline__ float silu_f(float v) {
    return v / (1.0f + __expf(-v));
}

// =====================================================================
// Kernel A: uv GEMM + h=u*silu(v) + y_out epilogue + ao partial outer-products
// =====================================================================
__global__ __launch_bounds__(256, 1)
void kA(const float* __restrict__ x, const float* __restrict__ y,
        const float* __restrict__ w_swiglu, const float* __restrict__ w_out,
        float* __restrict__ out)
{
    extern __shared__ float sm[];
    float* swT = sm;                    // [256][SWT_S]
    float* sy  = swT + SWT_SZ;          // [32][SY_S]
    float* so  = sy  + SY_SZ;           // [64][SO_S]
    float* suv = so  + SO_SZ;           // [32][SUV_S]
    float* sh  = suv + SUV_SZ;          // [32][SH_S]

    const int tid = threadIdx.x;

    // load w_swiglu [128][256] transposed -> swT[k][e]
    #pragma unroll
    for (int r = 0; r < 32; r++) {
        int i  = tid + r * 256;         // 0..8191
        int e  = i >> 6;                // 0..127
        int k4 = (i & 63) << 2;         // 0..252
        float4 wv = reinterpret_cast<const float4*>(w_swiglu)[i];
        swT[(k4 + 0) * SWT_S + e] = wv.x;
        swT[(k4 + 1) * SWT_S + e] = wv.y;
        swT[(k4 + 2) * SWT_S + e] = wv.z;
        swT[(k4 + 3) * SWT_S + e] = wv.w;
    }
    // load w_out [64][64] -> so
    #pragma unroll
    for (int r = 0; r < 4; r++) {
        int i  = tid + r * 256;         // 0..1023
        int e  = i >> 4;
        int d4 = (i & 15) << 2;
        float4 wv = reinterpret_cast<const float4*>(w_out)[i];
        *reinterpret_cast<float4*>(&so[e * SO_S + d4]) = wv;
    }

    // ao accumulators: thread owns 4x4 tile of 64x64
    float aoA[4][4];
    #pragma unroll
    for (int a = 0; a < 4; a++)
        #pragma unroll
        for (int b = 0; b < 4; b++) aoA[a][b] = 0.f;

    const int og   = tid & 31;          // out group (4 outs)
    const int tg   = tid >> 5;          // token group (4 tokens)
    const int eg   = tid & 15;          // epilogue e group
    const int tp   = tid >> 4;          // epilogue token pair
    const int dg   = tid & 15;          // ao d group
    const int eg2  = tid >> 4;          // ao e group
    const int tok0 = blockIdx.x * BLK_TOK;

    for (int sub = 0; sub < NSUB; sub++) {
        const int tbase = tok0 + sub * ST;

        __syncthreads();   // previous iter's suv/sh readers done
        // load y tile [32][256]
        #pragma unroll
        for (int r = 0; r < 8; r++) {
            int i  = tid + r * 256;     // 0..2047
            int t  = i >> 6;
            int k4 = (i & 63) << 2;
            float4 yv = reinterpret_cast<const float4*>(y)[(size_t)(tbase + t) * 64 + (i & 63)];
            *reinterpret_cast<float4*>(&sy[t * SY_S + k4]) = yv;
        }
        __syncthreads();

        // ---- GEMM: acc[t][o] = sum_k sy[t][k] * swT[k][o] ----
        float acc[4][4];
        #pragma unroll
        for (int a = 0; a < 4; a++)
            #pragma unroll
            for (int b = 0; b < 4; b++) acc[a][b] = 0.f;

        const float* yr0 = &sy[(tg * 4 + 0) * SY_S];
        const float* yr1 = &sy[(tg * 4 + 1) * SY_S];
        const float* yr2 = &sy[(tg * 4 + 2) * SY_S];
        const float* yr3 = &sy[(tg * 4 + 3) * SY_S];

        #pragma unroll 4
        for (int k = 0; k < 256; k += 4) {
            float wv[4][4];
            #pragma unroll
            for (int kk = 0; kk < 4; kk++) {
                float4 wt = *reinterpret_cast<const float4*>(&swT[(k + kk) * SWT_S + og * 4]);
                wv[kk][0] = wt.x; wv[kk][1] = wt.y; wv[kk][2] = wt.z; wv[kk][3] = wt.w;
            }
            float yv[4][4];
            float4 t0 = *reinterpret_cast<const float4*>(&yr0[k]);
            float4 t1 = *reinterpret_cast<const float4*>(&yr1[k]);
            float4 t2 = *reinterpret_cast<const float4*>(&yr2[k]);
            float4 t3 = *reinterpret_cast<const float4*>(&yr3[k]);
            yv[0][0]=t0.x; yv[0][1]=t0.y; yv[0][2]=t0.z; yv[0][3]=t0.w;
            yv[1][0]=t1.x; yv[1][1]=t1.y; yv[1][2]=t1.z; yv[1][3]=t1.w;
            yv[2][0]=t2.x; yv[2][1]=t2.y; yv[2][2]=t2.z; yv[2][3]=t2.w;
            yv[3][0]=t3.x; yv[3][1]=t3.y; yv[3][2]=t3.z; yv[3][3]=t3.w;
            #pragma unroll
            for (int kk = 0; kk < 4; kk++)
                #pragma unroll
                for (int t = 0; t < 4; t++)
                    #pragma unroll
                    for (int o = 0; o < 4; o++)
                        acc[t][o] += yv[t][kk] * wv[kk][o];
        }

        // write uv tile
        #pragma unroll
        for (int t = 0; t < 4; t++) {
            float4 v4 = make_float4(acc[t][0], acc[t][1], acc[t][2], acc[t][3]);
            *reinterpret_cast<float4*>(&suv[(tg * 4 + t) * SUV_S + og * 4]) = v4;
        }
        __syncthreads();

        // ---- h = u * silu(v) ----
        #pragma unroll
        for (int r = 0; r < 8; r++) {
            int i = tid + r * 256;      // 0..2047
            int t = i >> 6;
            int d = i & 63;
            float u = suv[t * SUV_S + d];
            float v = suv[t * SUV_S + 64 + d];
            sh[t * SH_S + d] = u * silu_f(v);
        }
        __syncthreads();

        // ---- epilogue: y_out = x + h @ w_out^T ----
        {
            const int t0 = tp * 2, t1 = t0 + 1;
            float4 x0 = *reinterpret_cast<const float4*>(&x[(size_t)(tbase + t0) * 64 + eg * 4]);
            float4 x1 = *reinterpret_cast<const float4*>(&x[(size_t)(tbase + t1) * 64 + eg * 4]);
            float a0[4] = {x0.x, x0.y, x0.z, x0.w};
            float a1[4] = {x1.x, x1.y, x1.z, x1.w};
            #pragma unroll
            for (int d = 0; d < 64; d += 4) {
                float4 h0v = *reinterpret_cast<const float4*>(&sh[t0 * SH_S + d]);
                float4 h1v = *reinterpret_cast<const float4*>(&sh[t1 * SH_S + d]);
                float h0[4] = {h0v.x, h0v.y, h0v.z, h0v.w};
                float h1[4] = {h1v.x, h1v.y, h1v.z, h1v.w};
                #pragma unroll
                for (int e4 = 0; e4 < 4; e4++) {
                    float4 wt = *reinterpret_cast<const float4*>(&so[(eg * 4 + e4) * SO_S + d]);
                    a0[e4] += h0[0]*wt.x + h0[1]*wt.y + h0[2]*wt.z + h0[3]*wt.w;
                    a1[e4] += h1[0]*wt.x + h1[1]*wt.y + h1[2]*wt.z + h1[3]*wt.w;
                }
            }
            *reinterpret_cast<float4*>(&out[(size_t)(tbase + t0) * 64 + eg * 4]) =
                make_float4(a0[0], a0[1], a0[2], a0[3]);
            *reinterpret_cast<float4*>(&out[(size_t)(tbase + t1) * 64 + eg * 4]) =
                make_float4(a1[0], a1[1], a1[2], a1[3]);
        }

        // ---- ao partial accumulation: ao[d][e] += u[t][d]*v[t][e] ----
        #pragma unroll 4
        for (int t = 0; t < 32; t++) {
            float4 u4 = *reinterpret_cast<const float4*>(&suv[t * SUV_S + dg * 4]);
            float4 v4 = *reinterpret_cast<const float4*>(&suv[t * SUV_S + 64 + eg2 * 4]);
            float uu[4] = {u4.x, u4.y, u4.z, u4.w};
            float vv[4] = {v4.x, v4.y, v4.z, v4.w};
            #pragma unroll
            for (int a = 0; a < 4; a++)
                #pragma unroll
                for (int b = 0; b < 4; b++)
                    aoA[a][b] += uu[a] * vv[b];
        }
    }

    // write ao partials
    float* dst = &g_aoPart[(size_t)blockIdx.x * 4096];
    #pragma unroll
    for (int a = 0; a < 4; a++)
        #pragma unroll
        for (int b = 0; b < 4; b++)
            dst[(dg * 4 + a) * 64 + (eg2 * 4 + b)] = aoA[a][b];
}

// =====================================================================
// Kernel B: reduce ao partials, /B * n^-0.5 (= /64), per-row rms-norm
// =====================================================================
__global__ __launch_bounds__(64)
void kB()
{
    const int d = blockIdx.x;
    const int e = threadIdx.x;
    float s = 0.f;
    const float* p = &g_aoPart[d * 64 + e];
    #pragma unroll 8
    for (int b = 0; b < NBLKA; b++) s += p[(size_t)b * 4096];
    s *= (1.0f / 64.0f);

    float q = s * s;
    #pragma unroll
    for (int o = 16; o > 0; o >>= 1) q += __shfl_down_sync(0xffffffff, q, o);
    __shared__ float tmp[2];
    if ((e & 31) == 0) tmp[e >> 5] = q;
    __syncthreads();
    float ms = (tmp[0] + tmp[1]) * (1.0f / 64.0f) + 1.1920929e-07f;
    g_ao[d * 64 + e] = s * rsqrtf(ms);
}

// =====================================================================
// Kernel C: weight updates (unnormalized), per-row stats
//   rows 0..767    : w_qkv    (m = w + silu(w@ao)@out_w^T)
//   rows 768..1279 : w_swiglu via X = reshape(64,512)^T
//   rows 1280..1343: w_out
// =====================================================================
__global__ __launch_bounds__(64)
void kC(const float* __restrict__ w_qkv, const float* __restrict__ w_swiglu,
        const float* __restrict__ w_out, const float* __restrict__ out_w,
        float* __restrict__ out)
{
    const int r = blockIdx.x;
    const int j = threadIdx.x;
    __shared__ float rv[64], nn[64];

    float base;
    if (r < 768)        base = w_qkv[r * 64 + j];
    else if (r < 1280)  base = w_swiglu[j * 512 + (r - 768)];
    else                base = w_out[(r - 1280) * 64 + j];
    rv[j] = base;
    __syncthreads();

    float a = 0.f;
    #pragma unroll 8
    for (int k = 0; k < 64; k++) a += rv[k] * g_ao[k * 64 + j];
    nn[j] = silu_f(a);
    __syncthreads();

    float m = base;
    #pragma unroll 8
    for (int k = 0; k < 64; k++) m += nn[k] * out_w[j * 64 + k];

    if (r < 768)        out[O1 + r * 64 + j] = m;
    else if (r < 1280)  out[O2 + j * 512 + (r - 768)] = m;
    else                out[O3 + (r - 1280) * 64 + j] = m;

    // row stats (sum, sumsq)
    float s = m, q = m * m;
    #pragma unroll
    for (int o = 16; o > 0; o >>= 1) {
        s += __shfl_down_sync(0xffffffff, s, o);
        q += __shfl_down_sync(0xffffffff, q, o);
    }
    __shared__ float t4[4];
    if ((j & 31) == 0) { t4[j >> 5] = s; t4[2 + (j >> 5)] = q; }
    __syncthreads();
    if (j == 0) g_rowstats[r] = make_float2(t4[0] + t4[1], t4[2] + t4[3]);
}

// =====================================================================
// Kernel D: per-matrix std (ddof=1) + gates -> g_scale[3]
// =====================================================================
__global__ __launch_bounds__(512)
void kD(const float* __restrict__ tao)
{
    const int tid = threadIdx.x;
    float s[3] = {0.f, 0.f, 0.f}, q[3] = {0.f, 0.f, 0.f};
    for (int r = tid; r < 1344; r += 512) {
        float2 v = g_rowstats[r];
        int m = (r < 768) ? 0 : ((r < 1280) ? 1 : 2);
        s[m] += v.x; q[m] += v.y;
    }
    __shared__ float red[6][512];
    #pragma unroll
    for (int m = 0; m < 3; m++) { red[m][tid] = s[m]; red[3 + m][tid] = q[m]; }
    __syncthreads();
    for (int step = 256; step > 0; step >>= 1) {
        if (tid < step) {
            #pragma unroll
            for (int c = 0; c < 6; c++) red[c][tid] += red[c][tid + step];
        }
        __syncthreads();
    }
    if (tid < 3) {
        float n      = (tid == 0) ? 49152.f : ((tid == 1) ? 32768.f : 4096.f);
        float target = (tid == 0) ? 0.125f : 0.0625f;
        float sum = red[tid][0], sq = red[3 + tid][0];
        float var = (sq - sum * sum / n) / (n - 1.f);
        var = fmaxf(var, 0.f);
        float sd = sqrtf(var);
        float gv = fminf(fmaxf(fabsf(tao[tid]), 1e-8f), 1.0f);
        g_scale[tid] = target / (sd + 1e-8f) * gv;
    }
}

// =====================================================================
// Kernel E: scale weight outputs in place
// =====================================================================
__global__ __launch_bounds__(256)
void kE(float* __restrict__ out)
{
    int i = blockIdx.x * 256 + threadIdx.x;
    if (i < 86016) {
        int m = (i < 49152) ? 0 : ((i < 81920) ? 1 : 2);
        out[O1 + i] *= g_scale[m];
    }
}

// =====================================================================
extern "C" void kernel_launch(void* const* d_in, const int* in_sizes, int n_in,
                              void* d_out, int out_size)
{
    const float* x        = (const float*)d_in[0];
    const float* y        = (const float*)d_in[1];
    const float* w_qkv    = (const float*)d_in[2];
    const float* w_swiglu = (const float*)d_in[3];
    const float* w_out    = (const float*)d_in[4];
    const float* out_w    = (const float*)d_in[5];
    const float* tao      = (const float*)d_in[6];
    float* out = (float*)d_out;

    cudaFuncSetAttribute(kA, cudaFuncAttributeMaxDynamicSharedMemorySize, SMEM_A_BYTES);
    kA<<<NBLKA, 256, SMEM_A_BYTES>>>(x, y, w_swiglu, w_out, out);
    kB<<<64, 64>>>();
    kC<<<1344, 64>>>(w_qkv, w_swiglu, w_out, out_w, out);
    kD<<<1, 512>>>(tao);
    kE<<<336, 256>>>(out);
}

// round 2
// speedup vs baseline: 1.0034x; 1.0034x over previous
#include <cuda_runtime.h>
#include <math.h>

// ---------------- problem constants ----------------
#define NT        65536      // B*T tokens
#define NBLKA     512
#define BLK_TOK   128
#define ST        32
#define NSUB      (BLK_TOK/ST)

#define O1 4194304           // w_qkv_new offset in d_out
#define O2 4243456           // w_swiglu_new offset
#define O3 4276224           // w_out_new offset

// smem strides (floats)
#define SWT_S 132            // swT[256][132]  (w_swiglu transposed)
#define SY_S  260            // sy [32][260]
#define SO_S  68             // so [64][68]    (w_out)
#define SUV_S 132            // suv[32][132]
#define SH_S  68             // sh [32][68]

#define SWT_SZ (256*SWT_S)
#define SY_SZ  (32*SY_S)
#define SO_SZ  (64*SO_S)
#define SUV_SZ (32*SUV_S)
#define SH_SZ  (32*SH_S)
#define SMEM_A_BYTES ((SWT_SZ+SY_SZ+SO_SZ+SUV_SZ+SH_SZ)*4)

// ---------------- device scratch (no allocations allowed) ----------------
__device__ float  g_aoPart[NBLKA * 4096];
__device__ float  g_ao[4096];
__device__ float2 g_rowstats[1344];
__device__ float  g_scale[3];

__device__ __forceinline__ float silu_f(float v) {
    return v / (1.0f + __expf(-v));
}

// =====================================================================
// Kernel A: uv GEMM + h=u*silu(v) + y_out epilogue + ao partial outer-products
// =====================================================================
__global__ __launch_bounds__(256, 1)
void kA(const float* __restrict__ x, const float* __restrict__ y,
        const float* __restrict__ w_swiglu, const float* __restrict__ w_out,
        float* __restrict__ out)
{
    extern __shared__ float sm[];
    float* swT = sm;                    // [256][SWT_S]
    float* sy  = swT + SWT_SZ;          // [32][SY_S]
    float* so  = sy  + SY_SZ;           // [64][SO_S]
    float* suv = so  + SO_SZ;           // [32][SUV_S]
    float* sh  = suv + SUV_SZ;          // [32][SH_S]

    const int tid = threadIdx.x;

    // load w_swiglu [128][256] transposed -> swT[k][e]
    #pragma unroll
    for (int r = 0; r < 32; r++) {
        int i  = tid + r * 256;         // 0..8191
        int e  = i >> 6;                // 0..127
        int k4 = (i & 63) << 2;         // 0..252
        float4 wv = reinterpret_cast<const float4*>(w_swiglu)[i];
        swT[(k4 + 0) * SWT_S + e] = wv.x;
        swT[(k4 + 1) * SWT_S + e] = wv.y;
        swT[(k4 + 2) * SWT_S + e] = wv.z;
        swT[(k4 + 3) * SWT_S + e] = wv.w;
    }
    // load w_out [64][64] -> so
    #pragma unroll
    for (int r = 0; r < 4; r++) {
        int i  = tid + r * 256;         // 0..1023
        int e  = i >> 4;
        int d4 = (i & 15) << 2;
        float4 wv = reinterpret_cast<const float4*>(w_out)[i];
        *reinterpret_cast<float4*>(&so[e * SO_S + d4]) = wv;
    }

    // ao accumulators: thread owns 4x4 tile of 64x64
    float aoA[4][4];
    #pragma unroll
    for (int a = 0; a < 4; a++)
        #pragma unroll
        for (int b = 0; b < 4; b++) aoA[a][b] = 0.f;

    const int og   = tid & 31;          // out group (4 outs)
    const int tg   = tid >> 5;          // token group (4 tokens)
    const int eg   = tid & 15;          // epilogue e group
    const int tp   = tid >> 4;          // epilogue token pair
    const int dg   = tid & 15;          // ao d group
    const int eg2  = tid >> 4;          // ao e group
    const int tok0 = blockIdx.x * BLK_TOK;

    for (int sub = 0; sub < NSUB; sub++) {
        const int tbase = tok0 + sub * ST;

        __syncthreads();   // previous iter's suv/sh readers done
        // load y tile [32][256]
        #pragma unroll
        for (int r = 0; r < 8; r++) {
            int i  = tid + r * 256;     // 0..2047
            int t  = i >> 6;
            int k4 = (i & 63) << 2;
            float4 yv = reinterpret_cast<const float4*>(y)[(size_t)(tbase + t) * 64 + (i & 63)];
            *reinterpret_cast<float4*>(&sy[t * SY_S + k4]) = yv;
        }
        __syncthreads();

        // ---- GEMM: acc[t][o] = sum_k sy[t][k] * swT[k][o] ----
        float acc[4][4];
        #pragma unroll
        for (int a = 0; a < 4; a++)
            #pragma unroll
            for (int b = 0; b < 4; b++) acc[a][b] = 0.f;

        const float* yr0 = &sy[(tg * 4 + 0) * SY_S];
        const float* yr1 = &sy[(tg * 4 + 1) * SY_S];
        const float* yr2 = &sy[(tg * 4 + 2) * SY_S];
        const float* yr3 = &sy[(tg * 4 + 3) * SY_S];

        #pragma unroll 4
        for (int k = 0; k < 256; k += 4) {
            float wv[4][4];
            #pragma unroll
            for (int kk = 0; kk < 4; kk++) {
                float4 wt = *reinterpret_cast<const float4*>(&swT[(k + kk) * SWT_S + og * 4]);
                wv[kk][0] = wt.x; wv[kk][1] = wt.y; wv[kk][2] = wt.z; wv[kk][3] = wt.w;
            }
            float yv[4][4];
            float4 t0 = *reinterpret_cast<const float4*>(&yr0[k]);
            float4 t1 = *reinterpret_cast<const float4*>(&yr1[k]);
            float4 t2 = *reinterpret_cast<const float4*>(&yr2[k]);
            float4 t3 = *reinterpret_cast<const float4*>(&yr3[k]);
            yv[0][0]=t0.x; yv[0][1]=t0.y; yv[0][2]=t0.z; yv[0][3]=t0.w;
            yv[1][0]=t1.x; yv[1][1]=t1.y; yv[1][2]=t1.z; yv[1][3]=t1.w;
            yv[2][0]=t2.x; yv[2][1]=t2.y; yv[2][2]=t2.z; yv[2][3]=t2.w;
            yv[3][0]=t3.x; yv[3][1]=t3.y; yv[3][2]=t3.z; yv[3][3]=t3.w;
            #pragma unroll
            for (int kk = 0; kk < 4; kk++)
                #pragma unroll
                for (int t = 0; t < 4; t++)
                    #pragma unroll
                    for (int o = 0; o < 4; o++)
                        acc[t][o] += yv[t][kk] * wv[kk][o];
        }

        // write uv tile
        #pragma unroll
        for (int t = 0; t < 4; t++) {
            float4 v4 = make_float4(acc[t][0], acc[t][1], acc[t][2], acc[t][3]);
            *reinterpret_cast<float4*>(&suv[(tg * 4 + t) * SUV_S + og * 4]) = v4;
        }
        __syncthreads();

        // ---- h = u * silu(v) ----
        #pragma unroll
        for (int r = 0; r < 8; r++) {
            int i = tid + r * 256;      // 0..2047
            int t = i >> 6;
            int d = i & 63;
            float u = suv[t * SUV_S + d];
            float v = suv[t * SUV_S + 64 + d];
            sh[t * SH_S + d] = u * silu_f(v);
        }
        __syncthreads();

        // ---- epilogue: y_out = x + h @ w_out^T ----
        {
            const int t0 = tp * 2, t1 = t0 + 1;
            float4 x0 = *reinterpret_cast<const float4*>(&x[(size_t)(tbase + t0) * 64 + eg * 4]);
            float4 x1 = *reinterpret_cast<const float4*>(&x[(size_t)(tbase + t1) * 64 + eg * 4]);
            float a0[4] = {x0.x, x0.y, x0.z, x0.w};
            float a1[4] = {x1.x, x1.y, x1.z, x1.w};
            #pragma unroll
            for (int d = 0; d < 64; d += 4) {
                float4 h0v = *reinterpret_cast<const float4*>(&sh[t0 * SH_S + d]);
                float4 h1v = *reinterpret_cast<const float4*>(&sh[t1 * SH_S + d]);
                float h0[4] = {h0v.x, h0v.y, h0v.z, h0v.w};
                float h1[4] = {h1v.x, h1v.y, h1v.z, h1v.w};
                #pragma unroll
                for (int e4 = 0; e4 < 4; e4++) {
                    float4 wt = *reinterpret_cast<const float4*>(&so[(eg * 4 + e4) * SO_S + d]);
                    a0[e4] += h0[0]*wt.x + h0[1]*wt.y + h0[2]*wt.z + h0[3]*wt.w;
                    a1[e4] += h1[0]*wt.x + h1[1]*wt.y + h1[2]*wt.z + h1[3]*wt.w;
                }
            }
            *reinterpret_cast<float4*>(&out[(size_t)(tbase + t0) * 64 + eg * 4]) =
                make_float4(a0[0], a0[1], a0[2], a0[3]);
            *reinterpret_cast<float4*>(&out[(size_t)(tbase + t1) * 64 + eg * 4]) =
                make_float4(a1[0], a1[1], a1[2], a1[3]);
        }

        // ---- ao partial accumulation: ao[d][e] += u[t][d]*v[t][e] ----
        #pragma unroll 4
        for (int t = 0; t < 32; t++) {
            float4 u4 = *reinterpret_cast<const float4*>(&suv[t * SUV_S + dg * 4]);
            float4 v4 = *reinterpret_cast<const float4*>(&suv[t * SUV_S + 64 + eg2 * 4]);
            float uu[4] = {u4.x, u4.y, u4.z, u4.w};
            float vv[4] = {v4.x, v4.y, v4.z, v4.w};
            #pragma unroll
            for (int a = 0; a < 4; a++)
                #pragma unroll
                for (int b = 0; b < 4; b++)
                    aoA[a][b] += uu[a] * vv[b];
        }
    }

    // write ao partials
    float* dst = &g_aoPart[(size_t)blockIdx.x * 4096];
    #pragma unroll
    for (int a = 0; a < 4; a++)
        #pragma unroll
        for (int b = 0; b < 4; b++)
            dst[(dg * 4 + a) * 64 + (eg2 * 4 + b)] = aoA[a][b];
}

// =====================================================================
// Kernel B: reduce ao partials, /B * n^-0.5 (= /64), per-row rms-norm
// =====================================================================
__global__ __launch_bounds__(64)
void kB()
{
    const int d = blockIdx.x;
    const int e = threadIdx.x;
    float s = 0.f;
    const float* p = &g_aoPart[d * 64 + e];
    #pragma unroll 8
    for (int b = 0; b < NBLKA; b++) s += p[(size_t)b * 4096];
    s *= (1.0f / 64.0f);

    float q = s * s;
    #pragma unroll
    for (int o = 16; o > 0; o >>= 1) q += __shfl_down_sync(0xffffffff, q, o);
    __shared__ float tmp[2];
    if ((e & 31) == 0) tmp[e >> 5] = q;
    __syncthreads();
    float ms = (tmp[0] + tmp[1]) * (1.0f / 64.0f) + 1.1920929e-07f;
    g_ao[d * 64 + e] = s * rsqrtf(ms);
}

// =====================================================================
// Kernel C: weight updates (unnormalized), per-row stats
//   rows 0..767    : w_qkv    (m = w + silu(w@ao)@out_w^T)
//   rows 768..1279 : w_swiglu via X = reshape(64,512)^T
//   rows 1280..1343: w_out
// =====================================================================
__global__ __launch_bounds__(64)
void kC(const float* __restrict__ w_qkv, const float* __restrict__ w_swiglu,
        const float* __restrict__ w_out, const float* __restrict__ out_w,
        float* __restrict__ out)
{
    const int r = blockIdx.x;
    const int j = threadIdx.x;
    __shared__ float rv[64], nn[64];

    float base;
    if (r < 768)        base = w_qkv[r * 64 + j];
    else if (r < 1280)  base = w_swiglu[j * 512 + (r - 768)];
    else                base = w_out[(r - 1280) * 64 + j];
    rv[j] = base;
    __syncthreads();

    float a = 0.f;
    #pragma unroll 8
    for (int k = 0; k < 64; k++) a += rv[k] * g_ao[k * 64 + j];
    nn[j] = silu_f(a);
    __syncthreads();

    float m = base;
    #pragma unroll 8
    for (int k = 0; k < 64; k++) m += nn[k] * out_w[j * 64 + k];

    if (r < 768)        out[O1 + r * 64 + j] = m;
    else if (r < 1280)  out[O2 + j * 512 + (r - 768)] = m;
    else                out[O3 + (r - 1280) * 64 + j] = m;

    // row stats (sum, sumsq)
    float s = m, q = m * m;
    #pragma unroll
    for (int o = 16; o > 0; o >>= 1) {
        s += __shfl_down_sync(0xffffffff, s, o);
        q += __shfl_down_sync(0xffffffff, q, o);
    }
    __shared__ float t4[4];
    if ((j & 31) == 0) { t4[j >> 5] = s; t4[2 + (j >> 5)] = q; }
    __syncthreads();
    if (j == 0) g_rowstats[r] = make_float2(t4[0] + t4[1], t4[2] + t4[3]);
}

// =====================================================================
// Kernel D: per-matrix std (ddof=1) + gates -> g_scale[3]
// =====================================================================
__global__ __launch_bounds__(512)
void kD(const float* __restrict__ tao)
{
    const int tid = threadIdx.x;
    float s[3] = {0.f, 0.f, 0.f}, q[3] = {0.f, 0.f, 0.f};
    for (int r = tid; r < 1344; r += 512) {
        float2 v = g_rowstats[r];
        int m = (r < 768) ? 0 : ((r < 1280) ? 1 : 2);
        s[m] += v.x; q[m] += v.y;
    }
    __shared__ float red[6][512];
    #pragma unroll
    for (int m = 0; m < 3; m++) { red[m][tid] = s[m]; red[3 + m][tid] = q[m]; }
    __syncthreads();
    for (int step = 256; step > 0; step >>= 1) {
        if (tid < step) {
            #pragma unroll
            for (int c = 0; c < 6; c++) red[c][tid] += red[c][tid + step];
        }
        __syncthreads();
    }
    if (tid < 3) {
        float n      = (tid == 0) ? 49152.f : ((tid == 1) ? 32768.f : 4096.f);
        float target = (tid == 0) ? 0.125f : 0.0625f;
        float sum = red[tid][0], sq = red[3 + tid][0];
        float var = (sq - sum * sum / n) / (n - 1.f);
        var = fmaxf(var, 0.f);
        float sd = sqrtf(var);
        float gv = fminf(fmaxf(fabsf(tao[tid]), 1e-8f), 1.0f);
        g_scale[tid] = target / (sd + 1e-8f) * gv;
    }
}

// =====================================================================
// Kernel E: scale weight outputs in place
// =====================================================================
__global__ __launch_bounds__(256)
void kE(float* __restrict__ out)
{
    int i = blockIdx.x * 256 + threadIdx.x;
    if (i < 86016) {
        int m = (i < 49152) ? 0 : ((i < 81920) ? 1 : 2);
        out[O1 + i] *= g_scale[m];
    }
}

// =====================================================================
extern "C" void kernel_launch(void* const* d_in, const int* in_sizes, int n_in,
                              void* d_out, int out_size)
{
    const float* x        = (const float*)d_in[0];
    const float* y        = (const float*)d_in[1];
    const float* w_qkv    = (const float*)d_in[2];
    const float* w_swiglu = (const float*)d_in[3];
    const float* w_out    = (const float*)d_in[4];
    const float* out_w    = (const float*)d_in[5];
    const float* tao      = (const float*)d_in[6];
    float* out = (float*)d_out;

    cudaFuncSetAttribute(kA, cudaFuncAttributeMaxDynamicSharedMemorySize, SMEM_A_BYTES);
    kA<<<NBLKA, 256, SMEM_A_BYTES>>>(x, y, w_swiglu, w_out, out);
    kB<<<64, 64>>>();
    kC<<<1344, 64>>>(w_qkv, w_swiglu, w_out, out_w, out);
    kD<<<1, 512>>>(tao);
    kE<<<336, 256>>>(out);
}

// round 4
// speedup vs baseline: 2.6205x; 2.6115x over previous
#include <cuda_runtime.h>
#include <cstdint>
#include <math.h>

// ---------------- output offsets ----------------
#define O1 4194304
#define O2 4243456
#define O3 4276224

// ---------------- smem layout (float indices) ----------------
#define SY_OFF   0         // phase1: y half   [128][132]
#define SW_OFF   16896     // phase1: w half   [128][132]
#define SU_OFF   0         // phase2: u fp32   [128][68]
#define SV_OFF   8704      // phase2: v fp32   [128][68]
#define SH_OFF   17408     // phase2: h tf32   [128][68]
#define SWO_OFF  33792     // w_out tf32       [64][68]
#define SMEM_FLOATS 38144
#define SMEM_BYTES  (SMEM_FLOATS * 4)

// ---------------- device scratch ----------------
__device__ float  g_aoPart[512 * 4096];
__device__ float  g_ao[4096];
__device__ float2 g_rowstats[1344];
__device__ float  g_scale[3];

__device__ __forceinline__ float silu_f(float v) {
    return __fdividef(v, 1.0f + __expf(-v));
}
__device__ __forceinline__ uint32_t f2tf32(float f) {
    uint32_t r; asm("cvt.rna.tf32.f32 %0, %1;" : "=r"(r) : "f"(f)); return r;
}
__device__ __forceinline__ float f2tf32f(float f) {
    return __uint_as_float(f2tf32(f));
}
__device__ __forceinline__ void mma_tf32(float c[4],
    uint32_t a0, uint32_t a1, uint32_t a2, uint32_t a3,
    uint32_t b0, uint32_t b1)
{
    asm volatile(
        "mma.sync.aligned.m16n8k8.row.col.f32.tf32.tf32.f32 "
        "{%0,%1,%2,%3},{%4,%5,%6,%7},{%8,%9},{%0,%1,%2,%3};"
        : "+f"(c[0]), "+f"(c[1]), "+f"(c[2]), "+f"(c[3])
        : "r"(a0), "r"(a1), "r"(a2), "r"(a3), "r"(b0), "r"(b1));
}
__device__ __forceinline__ uint32_t fu(const float* p) {
    return __float_as_uint(*p);
}

// =====================================================================
// Kernel A: 128-token tile per CTA, all matmuls via tf32 mma.sync
// =====================================================================
__global__ __launch_bounds__(256, 1)
void kA(const float* __restrict__ x, const float* __restrict__ y,
        const float* __restrict__ w_swiglu, const float* __restrict__ w_out,
        float* __restrict__ out)
{
    extern __shared__ float sm[];
    const int tid = threadIdx.x;
    const int wid = tid >> 5;
    const int lid = tid & 31;
    const int lg  = lid >> 2;       // 0..7
    const int lc  = lid & 3;        // 0..3
    const int wm  = wid & 1;        // warp m (2)
    const int wn  = wid >> 1;       // warp n (4)
    const int tok0 = blockIdx.x * 128;

    // ---- load w_out -> sWO (tf32) [64 e][68] ----
    float* sWO = sm + SWO_OFF;
    #pragma unroll
    for (int r = 0; r < 4; r++) {
        int i = tid + r * 256;              // 0..1023
        int e = i >> 4, d4 = (i & 15) << 2;
        float4 wv = reinterpret_cast<const float4*>(w_out)[i];
        float* p = &sWO[e * 68 + d4];
        p[0] = f2tf32f(wv.x); p[1] = f2tf32f(wv.y);
        p[2] = f2tf32f(wv.z); p[3] = f2tf32f(wv.w);
    }

    // ================= GEMM1: uv = y @ w_swiglu^T (K=256 in 2 halves) ==========
    float acc[4][4][4];
    #pragma unroll
    for (int a = 0; a < 4; a++)
        #pragma unroll
        for (int b = 0; b < 4; b++)
            #pragma unroll
            for (int k = 0; k < 4; k++) acc[a][b][k] = 0.f;

    float* sY = sm + SY_OFF;    // [128 t][132]
    float* sW = sm + SW_OFF;    // [128 e][132]

    for (int half = 0; half < 2; half++) {
        __syncthreads();
        // load y half (tf32)
        #pragma unroll
        for (int r = 0; r < 16; r++) {
            int i = tid + r * 256;          // 0..4095
            int t = i >> 5, c4 = i & 31;
            float4 yv = reinterpret_cast<const float4*>(y)[(size_t)(tok0 + t) * 64 + half * 32 + c4];
            float* p = &sY[t * 132 + c4 * 4];
            p[0] = f2tf32f(yv.x); p[1] = f2tf32f(yv.y);
            p[2] = f2tf32f(yv.z); p[3] = f2tf32f(yv.w);
        }
        // load w half (tf32)
        #pragma unroll
        for (int r = 0; r < 16; r++) {
            int i = tid + r * 256;
            int e = i >> 5, c4 = i & 31;
            float4 wv = reinterpret_cast<const float4*>(w_swiglu)[(size_t)e * 64 + half * 32 + c4];
            float* p = &sW[e * 132 + c4 * 4];
            p[0] = f2tf32f(wv.x); p[1] = f2tf32f(wv.y);
            p[2] = f2tf32f(wv.z); p[3] = f2tf32f(wv.w);
        }
        __syncthreads();

        #pragma unroll
        for (int ks = 0; ks < 16; ks++) {
            const int kk = ks * 8;
            uint32_t A[4][4];
            #pragma unroll
            for (int mt = 0; mt < 4; mt++) {
                const float* p = &sY[(wm * 64 + mt * 16 + lg) * 132 + kk + lc];
                A[mt][0] = fu(p); A[mt][1] = fu(p + 8 * 132);
                A[mt][2] = fu(p + 4); A[mt][3] = fu(p + 8 * 132 + 4);
            }
            uint32_t B[4][2];
            #pragma unroll
            for (int nt = 0; nt < 4; nt++) {
                const float* p = &sW[(wn * 32 + nt * 8 + lg) * 132 + kk + lc];
                B[nt][0] = fu(p); B[nt][1] = fu(p + 4);
            }
            #pragma unroll
            for (int mt = 0; mt < 4; mt++)
                #pragma unroll
                for (int nt = 0; nt < 4; nt++)
                    mma_tf32(acc[mt][nt], A[mt][0], A[mt][1], A[mt][2], A[mt][3],
                             B[nt][0], B[nt][1]);
        }
    }
    __syncthreads();    // done reading sY/sW

    // ---- store uv fragments -> sU (fp32), sV (fp32) ----
    float* sU = sm + SU_OFF;    // [128 t][68]
    float* sV = sm + SV_OFF;    // [128 t][68]
    {
        float* dst = (wn < 2) ? sU : sV;
        const int cbase = (wn & 1) * 32;
        #pragma unroll
        for (int mt = 0; mt < 4; mt++) {
            int row = wm * 64 + mt * 16 + lg;
            #pragma unroll
            for (int nt = 0; nt < 4; nt++) {
                int cb = cbase + nt * 8 + 2 * lc;
                *reinterpret_cast<float2*>(&dst[row * 68 + cb]) =
                    make_float2(acc[mt][nt][0], acc[mt][nt][1]);
                *reinterpret_cast<float2*>(&dst[(row + 8) * 68 + cb]) =
                    make_float2(acc[mt][nt][2], acc[mt][nt][3]);
            }
        }
    }
    __syncthreads();

    // ---- h = u * silu(v) -> sH (tf32) ----
    float* sH = sm + SH_OFF;    // [128 t][68]
    #pragma unroll
    for (int r = 0; r < 32; r++) {
        int i = tid + r * 256;              // 0..8191
        int t = i >> 6, d = i & 63;
        float u = sU[t * 68 + d];
        float v = sV[t * 68 + d];
        sH[t * 68 + d] = f2tf32f(u * silu_f(v));
    }
    __syncthreads();

    // ================= Epilogue MMA: y_part = h @ w_out^T (M=128,N=64,K=64) ====
    float acc2[4][2][4];
    #pragma unroll
    for (int a = 0; a < 4; a++)
        #pragma unroll
        for (int b = 0; b < 2; b++)
            #pragma unroll
            for (int k = 0; k < 4; k++) acc2[a][b][k] = 0.f;

    #pragma unroll
    for (int ks = 0; ks < 8; ks++) {
        const int kk = ks * 8;
        uint32_t A[4][4];
        #pragma unroll
        for (int mt = 0; mt < 4; mt++) {
            const float* p = &sH[(wm * 64 + mt * 16 + lg) * 68 + kk + lc];
            A[mt][0] = fu(p); A[mt][1] = fu(p + 8 * 68);
            A[mt][2] = fu(p + 4); A[mt][3] = fu(p + 8 * 68 + 4);
        }
        uint32_t B[2][2];
        #pragma unroll
        for (int nt = 0; nt < 2; nt++) {
            const float* p = &sWO[(wn * 16 + nt * 8 + lg) * 68 + kk + lc];
            B[nt][0] = fu(p); B[nt][1] = fu(p + 4);
        }
        #pragma unroll
        for (int mt = 0; mt < 4; mt++)
            #pragma unroll
            for (int nt = 0; nt < 2; nt++)
                mma_tf32(acc2[mt][nt], A[mt][0], A[mt][1], A[mt][2], A[mt][3],
                         B[nt][0], B[nt][1]);
    }

    // write y_out = x + y_part
    #pragma unroll
    for (int mt = 0; mt < 4; mt++) {
        #pragma unroll
        for (int nt = 0; nt < 2; nt++) {
            int row = wm * 64 + mt * 16 + lg;
            int col = wn * 16 + nt * 8 + 2 * lc;
            size_t o0 = (size_t)(tok0 + row) * 64 + col;
            size_t o1 = (size_t)(tok0 + row + 8) * 64 + col;
            float2 x0 = *reinterpret_cast<const float2*>(&x[o0]);
            float2 x1 = *reinterpret_cast<const float2*>(&x[o1]);
            *reinterpret_cast<float2*>(&out[o0]) =
                make_float2(x0.x + acc2[mt][nt][0], x0.y + acc2[mt][nt][1]);
            *reinterpret_cast<float2*>(&out[o1]) =
                make_float2(x1.x + acc2[mt][nt][2], x1.y + acc2[mt][nt][3]);
        }
    }

    // ================= ao MMA: ao[d][e] = sum_t u[t][d] v[t][e] (M=64,N=64,K=128)
    float acc3[2][2][4];
    #pragma unroll
    for (int a = 0; a < 2; a++)
        #pragma unroll
        for (int b = 0; b < 2; b++)
            #pragma unroll
            for (int k = 0; k < 4; k++) acc3[a][b][k] = 0.f;

    #pragma unroll
    for (int ks = 0; ks < 16; ks++) {
        const int kk = ks * 8;
        uint32_t A[2][4];
        #pragma unroll
        for (int mt = 0; mt < 2; mt++) {
            int rb = wm * 32 + mt * 16;
            A[mt][0] = f2tf32(sU[(kk + lc) * 68 + rb + lg]);
            A[mt][1] = f2tf32(sU[(kk + lc) * 68 + rb + lg + 8]);
            A[mt][2] = f2tf32(sU[(kk + lc + 4) * 68 + rb + lg]);
            A[mt][3] = f2tf32(sU[(kk + lc + 4) * 68 + rb + lg + 8]);
        }
        uint32_t B[2][2];
        #pragma unroll
        for (int nt = 0; nt < 2; nt++) {
            int nb = wn * 16 + nt * 8;
            B[nt][0] = f2tf32(sV[(kk + lc) * 68 + nb + lg]);
            B[nt][1] = f2tf32(sV[(kk + lc + 4) * 68 + nb + lg]);
        }
        #pragma unroll
        for (int mt = 0; mt < 2; mt++)
            #pragma unroll
            for (int nt = 0; nt < 2; nt++)
                mma_tf32(acc3[mt][nt], A[mt][0], A[mt][1], A[mt][2], A[mt][3],
                         B[nt][0], B[nt][1]);
    }

    // write ao partials
    float* dst = g_aoPart + (size_t)blockIdx.x * 4096;
    #pragma unroll
    for (int mt = 0; mt < 2; mt++) {
        #pragma unroll
        for (int nt = 0; nt < 2; nt++) {
            int row = wm * 32 + mt * 16 + lg;
            int col = wn * 16 + nt * 8 + 2 * lc;
            *reinterpret_cast<float2*>(&dst[row * 64 + col]) =
                make_float2(acc3[mt][nt][0], acc3[mt][nt][1]);
            *reinterpret_cast<float2*>(&dst[(row + 8) * 64 + col]) =
                make_float2(acc3[mt][nt][2], acc3[mt][nt][3]);
        }
    }
}

// =====================================================================
// Kernel B: reduce ao partials, /64, per-row rms-norm
// =====================================================================
__global__ __launch_bounds__(64)
void kB()
{
    const int d = blockIdx.x;
    const int e = threadIdx.x;
    float s = 0.f;
    const float* p = &g_aoPart[d * 64 + e];
    #pragma unroll 8
    for (int b = 0; b < 512; b++) s += p[(size_t)b * 4096];
    s *= (1.0f / 64.0f);

    float q = s * s;
    #pragma unroll
    for (int o = 16; o > 0; o >>= 1) q += __shfl_down_sync(0xffffffff, q, o);
    __shared__ float tmp[2];
    if ((e & 31) == 0) tmp[e >> 5] = q;
    __syncthreads();
    float ms = (tmp[0] + tmp[1]) * (1.0f / 64.0f) + 1.1920929e-07f;
    g_ao[d * 64 + e] = s * rsqrtf(ms);
}

// =====================================================================
// Kernel C: weight updates (unnormalized) + per-row stats
// =====================================================================
__global__ __launch_bounds__(64)
void kC(const float* __restrict__ w_qkv, const float* __restrict__ w_swiglu,
        const float* __restrict__ w_out, const float* __restrict__ out_w,
        float* __restrict__ out)
{
    const int r = blockIdx.x;
    const int j = threadIdx.x;
    __shared__ float rv[64], nn[64];

    float base;
    if (r < 768)        base = w_qkv[r * 64 + j];
    else if (r < 1280)  base = w_swiglu[j * 512 + (r - 768)];
    else                base = w_out[(r - 1280) * 64 + j];
    rv[j] = base;
    __syncthreads();

    float a = 0.f;
    #pragma unroll 8
    for (int k = 0; k < 64; k++) a += rv[k] * g_ao[k * 64 + j];
    nn[j] = silu_f(a);
    __syncthreads();

    float m = base;
    #pragma unroll 8
    for (int k = 0; k < 64; k++) m += nn[k] * out_w[j * 64 + k];

    if (r < 768)        out[O1 + r * 64 + j] = m;
    else if (r < 1280)  out[O2 + j * 512 + (r - 768)] = m;
    else                out[O3 + (r - 1280) * 64 + j] = m;

    float s = m, q = m * m;
    #pragma unroll
    for (int o = 16; o > 0; o >>= 1) {
        s += __shfl_down_sync(0xffffffff, s, o);
        q += __shfl_down_sync(0xffffffff, q, o);
    }
    __shared__ float t4[4];
    if ((j & 31) == 0) { t4[j >> 5] = s; t4[2 + (j >> 5)] = q; }
    __syncthreads();
    if (j == 0) g_rowstats[r] = make_float2(t4[0] + t4[1], t4[2] + t4[3]);
}

// =====================================================================
// Kernel D: per-matrix std (ddof=1) + gates -> g_scale[3]
// =====================================================================
__global__ __launch_bounds__(512)
void kD(const float* __restrict__ tao)
{
    const int tid = threadIdx.x;
    float s[3] = {0.f, 0.f, 0.f}, q[3] = {0.f, 0.f, 0.f};
    for (int r = tid; r < 1344; r += 512) {
        float2 v = g_rowstats[r];
        int m = (r < 768) ? 0 : ((r < 1280) ? 1 : 2);
        s[m] += v.x; q[m] += v.y;
    }
    __shared__ float red[6][512];
    #pragma unroll
    for (int m = 0; m < 3; m++) { red[m][tid] = s[m]; red[3 + m][tid] = q[m]; }
    __syncthreads();
    for (int step = 256; step > 0; step >>= 1) {
        if (tid < step) {
            #pragma unroll
            for (int c = 0; c < 6; c++) red[c][tid] += red[c][tid + step];
        }
        __syncthreads();
    }
    if (tid < 3) {
        float n      = (tid == 0) ? 49152.f : ((tid == 1) ? 32768.f : 4096.f);
        float target = (tid == 0) ? 0.125f : 0.0625f;
        float sum = red[tid][0], sq = red[3 + tid][0];
        float var = (sq - sum * sum / n) / (n - 1.f);
        var = fmaxf(var, 0.f);
        float sd = sqrtf(var);
        float gv = fminf(fmaxf(fabsf(tao[tid]), 1e-8f), 1.0f);
        g_scale[tid] = target / (sd + 1e-8f) * gv;
    }
}

// =====================================================================
// Kernel E: scale weight outputs in place
// =====================================================================
__global__ __launch_bounds__(256)
void kE(float* __restrict__ out)
{
    int i = blockIdx.x * 256 + threadIdx.x;
    if (i < 86016) {
        int m = (i < 49152) ? 0 : ((i < 81920) ? 1 : 2);
        out[O1 + i] *= g_scale[m];
    }
}

// =====================================================================
extern "C" void kernel_launch(void* const* d_in, const int* in_sizes, int n_in,
                              void* d_out, int out_size)
{
    const float* x        = (const float*)d_in[0];
    const float* y        = (const float*)d_in[1];
    const float* w_qkv    = (const float*)d_in[2];
    const float* w_swiglu = (const float*)d_in[3];
    const float* w_out    = (const float*)d_in[4];
    const float* out_w    = (const float*)d_in[5];
    const float* tao      = (const float*)d_in[6];
    float* out = (float*)d_out;

    cudaFuncSetAttribute(kA, cudaFuncAttributeMaxDynamicSharedMemorySize, SMEM_BYTES);
    kA<<<512, 256, SMEM_BYTES>>>(x, y, w_swiglu, w_out, out);
    kB<<<64, 64>>>();
    kC<<<1344, 64>>>(w_qkv, w_swiglu, w_out, out_w, out);
    kD<<<1, 512>>>(tao);
    kE<<<336, 256>>>(out);
}

// round 5
// speedup vs baseline: 2.7679x; 1.0563x over previous
#include <cuda_runtime.h>
#include <cstdint>
#include <math.h>

// ---------------- output offsets ----------------
#define O1 4194304
#define O2 4243456
#define O3 4276224

// ---------------- smem layout (float indices) ----------------
#define SWO_OFF 0        // w_out tf32 [64][68]
#define SY0_OFF 4352     // y chunk buf0 [128][68]  -> phase2: sU
#define SY1_OFF 13056    // y chunk buf1 [128][68]  -> phase2: sV
#define SW0_OFF 21760    // w chunk buf0 [128][68]  -> phase2: sH
#define SW1_OFF 30464    // w chunk buf1 [128][68]
#define SMEM_FLOATS 39168
#define SMEM_BYTES (SMEM_FLOATS * 4)

// ---------------- device scratch ----------------
__device__ float  g_aoPart[512 * 4096];
__device__ float  g_ao[4096];
__device__ float2 g_rowstats[1344];
__device__ float  g_scale[3];

__device__ __forceinline__ float silu_f(float v) {
    return __fdividef(v, 1.0f + __expf(-v));
}
__device__ __forceinline__ uint32_t f2tf32(float f) {
    uint32_t r; asm("cvt.rna.tf32.f32 %0, %1;" : "=r"(r) : "f"(f)); return r;
}
__device__ __forceinline__ float f2tf32f(float f) {
    return __uint_as_float(f2tf32(f));
}
__device__ __forceinline__ void mma_tf32(float c[4],
    uint32_t a0, uint32_t a1, uint32_t a2, uint32_t a3,
    uint32_t b0, uint32_t b1)
{
    asm volatile(
        "mma.sync.aligned.m16n8k8.row.col.f32.tf32.tf32.f32 "
        "{%0,%1,%2,%3},{%4,%5,%6,%7},{%8,%9},{%0,%1,%2,%3};"
        : "+f"(c[0]), "+f"(c[1]), "+f"(c[2]), "+f"(c[3])
        : "r"(a0), "r"(a1), "r"(a2), "r"(a3), "r"(b0), "r"(b1));
}

// =====================================================================
// Kernel A: 128-token tile per CTA; all matmuls via tf32 mma.sync
//   GEMM1 pipelined over 4 k-chunks of 64 with double-buffered smem.
//   Fragment loads vectorized via k-permutation (lane lc <-> k 2lc,
//   lane lc+4 <-> k 2lc+1; consistent on A and B).
// =====================================================================
__global__ __launch_bounds__(256, 1)
void kA(const float* __restrict__ x, const float* __restrict__ y,
        const float* __restrict__ w_swiglu, const float* __restrict__ w_out,
        float* __restrict__ out)
{
    extern __shared__ float sm[];
    const int tid = threadIdx.x;
    const int lid = tid & 31;
    const int wid = tid >> 5;
    const int lg  = lid >> 2;       // 0..7
    const int lc  = lid & 3;        // 0..3
    const int wm  = wid & 1;        // 2 warps over M
    const int wn  = wid >> 1;       // 4 warps over N
    const int tok0 = blockIdx.x * 128;

    const float4* yf4 = reinterpret_cast<const float4*>(y);
    const float4* wf4 = reinterpret_cast<const float4*>(w_swiglu);

    // ---- load w_out -> sWO (tf32) [64][68] ----
    float* sWO = sm + SWO_OFF;
    #pragma unroll
    for (int r = 0; r < 4; r++) {
        int i = tid + r * 256;              // 0..1023
        int e = i >> 4, d4 = (i & 15) << 2;
        float4 wv = reinterpret_cast<const float4*>(w_out)[i];
        *reinterpret_cast<float4*>(&sWO[e * 68 + d4]) =
            make_float4(f2tf32f(wv.x), f2tf32f(wv.y), f2tf32f(wv.z), f2tf32f(wv.w));
    }

    // ================= GEMM1: uv = y @ w_swiglu^T, K=256 in 4 chunks ==========
    float acc[4][4][4];
    #pragma unroll
    for (int a = 0; a < 4; a++)
        #pragma unroll
        for (int b = 0; b < 4; b++)
            #pragma unroll
            for (int k = 0; k < 4; k++) acc[a][b][k] = 0.f;

    float* const bufY[2] = { sm + SY0_OFF, sm + SY1_OFF };
    float* const bufW[2] = { sm + SW0_OFF, sm + SW1_OFF };

    const int ldrow = tid >> 4;             // 0..15 base row group
    const int ldc4  = tid & 15;             // float4 col within 64-chunk

    float4 ry[8], rw[8];

    // prefetch chunk 0
    #pragma unroll
    for (int r = 0; r < 8; r++) {
        int row = ldrow + r * 16;
        ry[r] = yf4[(size_t)(tok0 + row) * 64 + ldc4];
        rw[r] = wf4[(size_t)row * 64 + ldc4];
    }
    #pragma unroll
    for (int r = 0; r < 8; r++) {
        int row = ldrow + r * 16;
        *reinterpret_cast<float4*>(&bufY[0][row * 68 + ldc4 * 4]) =
            make_float4(f2tf32f(ry[r].x), f2tf32f(ry[r].y), f2tf32f(ry[r].z), f2tf32f(ry[r].w));
        *reinterpret_cast<float4*>(&bufW[0][row * 68 + ldc4 * 4]) =
            make_float4(f2tf32f(rw[r].x), f2tf32f(rw[r].y), f2tf32f(rw[r].z), f2tf32f(rw[r].w));
    }
    __syncthreads();

    #pragma unroll
    for (int c = 0; c < 4; c++) {
        // issue next chunk's global loads early
        if (c < 3) {
            #pragma unroll
            for (int r = 0; r < 8; r++) {
                int row = ldrow + r * 16;
                ry[r] = yf4[(size_t)(tok0 + row) * 64 + (c + 1) * 16 + ldc4];
                rw[r] = wf4[(size_t)row * 64 + (c + 1) * 16 + ldc4];
            }
        }

        // MMA over this chunk (8 k-steps of 8)
        const float* bY = bufY[c & 1];
        const float* bW = bufW[c & 1];
        #pragma unroll
        for (int ks = 0; ks < 8; ks++) {
            const int kk = ks * 8 + 2 * lc;
            uint32_t A[4][4];
            #pragma unroll
            for (int mt = 0; mt < 4; mt++) {
                const float* p = &bY[(wm * 64 + mt * 16 + lg) * 68 + kk];
                float2 a0 = *reinterpret_cast<const float2*>(p);
                float2 a1 = *reinterpret_cast<const float2*>(p + 8 * 68);
                A[mt][0] = __float_as_uint(a0.x); A[mt][2] = __float_as_uint(a0.y);
                A[mt][1] = __float_as_uint(a1.x); A[mt][3] = __float_as_uint(a1.y);
            }
            uint32_t B[4][2];
            #pragma unroll
            for (int nt = 0; nt < 4; nt++) {
                float2 bv = *reinterpret_cast<const float2*>(&bW[(wn * 32 + nt * 8 + lg) * 68 + kk]);
                B[nt][0] = __float_as_uint(bv.x); B[nt][1] = __float_as_uint(bv.y);
            }
            #pragma unroll
            for (int mt = 0; mt < 4; mt++)
                #pragma unroll
                for (int nt = 0; nt < 4; nt++)
                    mma_tf32(acc[mt][nt], A[mt][0], A[mt][1], A[mt][2], A[mt][3],
                             B[nt][0], B[nt][1]);
        }

        // store next chunk into the other buffer
        if (c < 3) {
            float* dY = bufY[(c + 1) & 1];
            float* dW = bufW[(c + 1) & 1];
            #pragma unroll
            for (int r = 0; r < 8; r++) {
                int row = ldrow + r * 16;
                *reinterpret_cast<float4*>(&dY[row * 68 + ldc4 * 4]) =
                    make_float4(f2tf32f(ry[r].x), f2tf32f(ry[r].y), f2tf32f(ry[r].z), f2tf32f(ry[r].w));
                *reinterpret_cast<float4*>(&dW[row * 68 + ldc4 * 4]) =
                    make_float4(f2tf32f(rw[r].x), f2tf32f(rw[r].y), f2tf32f(rw[r].z), f2tf32f(rw[r].w));
            }
        }
        __syncthreads();
    }

    // ---- store uv fragments -> sU (fp32), sV (fp32) ----
    float* sU = sm + SY0_OFF;   // [128][68]
    float* sV = sm + SY1_OFF;   // [128][68]
    {
        float* dst = (wn < 2) ? sU : sV;
        const int cbase = (wn & 1) * 32;
        #pragma unroll
        for (int mt = 0; mt < 4; mt++) {
            int row = wm * 64 + mt * 16 + lg;
            #pragma unroll
            for (int nt = 0; nt < 4; nt++) {
                int cb = cbase + nt * 8 + 2 * lc;
                *reinterpret_cast<float2*>(&dst[row * 68 + cb]) =
                    make_float2(acc[mt][nt][0], acc[mt][nt][1]);
                *reinterpret_cast<float2*>(&dst[(row + 8) * 68 + cb]) =
                    make_float2(acc[mt][nt][2], acc[mt][nt][3]);
            }
        }
    }
    __syncthreads();

    // ---- h = u * silu(v) -> sH (tf32) ----
    float* sH = sm + SW0_OFF;   // [128][68]
    #pragma unroll
    for (int r = 0; r < 8; r++) {
        int i = tid + r * 256;              // 0..2047 float4s
        int t = i >> 4, d4 = (i & 15) << 2;
        float4 u4 = *reinterpret_cast<const float4*>(&sU[t * 68 + d4]);
        float4 v4 = *reinterpret_cast<const float4*>(&sV[t * 68 + d4]);
        *reinterpret_cast<float4*>(&sH[t * 68 + d4]) = make_float4(
            f2tf32f(u4.x * silu_f(v4.x)), f2tf32f(u4.y * silu_f(v4.y)),
            f2tf32f(u4.z * silu_f(v4.z)), f2tf32f(u4.w * silu_f(v4.w)));
    }
    __syncthreads();

    // ---- prefetch x fragments for the output add ----
    float2 xr[4][2][2];
    #pragma unroll
    for (int mt = 0; mt < 4; mt++)
        #pragma unroll
        for (int nt = 0; nt < 2; nt++) {
            int row = wm * 64 + mt * 16 + lg;
            int col = wn * 16 + nt * 8 + 2 * lc;
            xr[mt][nt][0] = *reinterpret_cast<const float2*>(&x[(size_t)(tok0 + row) * 64 + col]);
            xr[mt][nt][1] = *reinterpret_cast<const float2*>(&x[(size_t)(tok0 + row + 8) * 64 + col]);
        }

    // ================= Epilogue MMA: y_part = h @ w_out^T (M=128,N=64,K=64) ====
    float acc2[4][2][4];
    #pragma unroll
    for (int a = 0; a < 4; a++)
        #pragma unroll
        for (int b = 0; b < 2; b++)
            #pragma unroll
            for (int k = 0; k < 4; k++) acc2[a][b][k] = 0.f;

    #pragma unroll
    for (int ks = 0; ks < 8; ks++) {
        const int kk = ks * 8 + 2 * lc;
        uint32_t A[4][4];
        #pragma unroll
        for (int mt = 0; mt < 4; mt++) {
            const float* p = &sH[(wm * 64 + mt * 16 + lg) * 68 + kk];
            float2 a0 = *reinterpret_cast<const float2*>(p);
            float2 a1 = *reinterpret_cast<const float2*>(p + 8 * 68);
            A[mt][0] = __float_as_uint(a0.x); A[mt][2] = __float_as_uint(a0.y);
            A[mt][1] = __float_as_uint(a1.x); A[mt][3] = __float_as_uint(a1.y);
        }
        uint32_t B[2][2];
        #pragma unroll
        for (int nt = 0; nt < 2; nt++) {
            float2 bv = *reinterpret_cast<const float2*>(&sWO[(wn * 16 + nt * 8 + lg) * 68 + kk]);
            B[nt][0] = __float_as_uint(bv.x); B[nt][1] = __float_as_uint(bv.y);
        }
        #pragma unroll
        for (int mt = 0; mt < 4; mt++)
            #pragma unroll
            for (int nt = 0; nt < 2; nt++)
                mma_tf32(acc2[mt][nt], A[mt][0], A[mt][1], A[mt][2], A[mt][3],
                         B[nt][0], B[nt][1]);
    }

    // write y_out = x + y_part
    #pragma unroll
    for (int mt = 0; mt < 4; mt++) {
        #pragma unroll
        for (int nt = 0; nt < 2; nt++) {
            int row = wm * 64 + mt * 16 + lg;
            int col = wn * 16 + nt * 8 + 2 * lc;
            size_t o0 = (size_t)(tok0 + row) * 64 + col;
            size_t o1 = (size_t)(tok0 + row + 8) * 64 + col;
            *reinterpret_cast<float2*>(&out[o0]) =
                make_float2(xr[mt][nt][0].x + acc2[mt][nt][0], xr[mt][nt][0].y + acc2[mt][nt][1]);
            *reinterpret_cast<float2*>(&out[o1]) =
                make_float2(xr[mt][nt][1].x + acc2[mt][nt][2], xr[mt][nt][1].y + acc2[mt][nt][3]);
        }
    }

    // ================= ao MMA: ao[d][e] = sum_t u[t][d] v[t][e] ================
    float acc3[2][2][4];
    #pragma unroll
    for (int a = 0; a < 2; a++)
        #pragma unroll
        for (int b = 0; b < 2; b++)
            #pragma unroll
            for (int k = 0; k < 4; k++) acc3[a][b][k] = 0.f;

    #pragma unroll
    for (int ks = 0; ks < 16; ks++) {
        const int kk = ks * 8;
        const int t0 = kk + 2 * lc;         // k-lane lc
        const int t1 = kk + 2 * lc + 1;     // k-lane lc+4
        uint32_t A[2][4];
        #pragma unroll
        for (int mt = 0; mt < 2; mt++) {
            int rb = wm * 32 + mt * 16;
            A[mt][0] = f2tf32(sU[t0 * 68 + rb + lg]);
            A[mt][1] = f2tf32(sU[t0 * 68 + rb + lg + 8]);
            A[mt][2] = f2tf32(sU[t1 * 68 + rb + lg]);
            A[mt][3] = f2tf32(sU[t1 * 68 + rb + lg + 8]);
        }
        uint32_t B[2][2];
        #pragma unroll
        for (int nt = 0; nt < 2; nt++) {
            int nb = wn * 16 + nt * 8;
            B[nt][0] = f2tf32(sV[t0 * 68 + nb + lg]);
            B[nt][1] = f2tf32(sV[t1 * 68 + nb + lg]);
        }
        #pragma unroll
        for (int mt = 0; mt < 2; mt++)
            #pragma unroll
            for (int nt = 0; nt < 2; nt++)
                mma_tf32(acc3[mt][nt], A[mt][0], A[mt][1], A[mt][2], A[mt][3],
                         B[nt][0], B[nt][1]);
    }

    // write ao partials
    float* dst = g_aoPart + (size_t)blockIdx.x * 4096;
    #pragma unroll
    for (int mt = 0; mt < 2; mt++) {
        #pragma unroll
        for (int nt = 0; nt < 2; nt++) {
            int row = wm * 32 + mt * 16 + lg;
            int col = wn * 16 + nt * 8 + 2 * lc;
            *reinterpret_cast<float2*>(&dst[row * 64 + col]) =
                make_float2(acc3[mt][nt][0], acc3[mt][nt][1]);
            *reinterpret_cast<float2*>(&dst[(row + 8) * 64 + col]) =
                make_float2(acc3[mt][nt][2], acc3[mt][nt][3]);
        }
    }
}

// =====================================================================
// Kernel B: reduce ao partials, /64, per-row rms-norm
// =====================================================================
__global__ __launch_bounds__(64)
void kB()
{
    const int d = blockIdx.x;
    const int e = threadIdx.x;
    float s = 0.f;
    const float* p = &g_aoPart[d * 64 + e];
    #pragma unroll 16
    for (int b = 0; b < 512; b++) s += p[(size_t)b * 4096];
    s *= (1.0f / 64.0f);

    float q = s * s;
    #pragma unroll
    for (int o = 16; o > 0; o >>= 1) q += __shfl_down_sync(0xffffffff, q, o);
    __shared__ float tmp[2];
    if ((e & 31) == 0) tmp[e >> 5] = q;
    __syncthreads();
    float ms = (tmp[0] + tmp[1]) * (1.0f / 64.0f) + 1.1920929e-07f;
    g_ao[d * 64 + e] = s * rsqrtf(ms);
}

// =====================================================================
// Kernel C: weight updates (unnormalized) + per-row stats
// =====================================================================
__global__ __launch_bounds__(64)
void kC(const float* __restrict__ w_qkv, const float* __restrict__ w_swiglu,
        const float* __restrict__ w_out, const float* __restrict__ out_w,
        float* __restrict__ out)
{
    const int r = blockIdx.x;
    const int j = threadIdx.x;
    __shared__ float rv[64], nn[64];

    float base;
    if (r < 768)        base = w_qkv[r * 64 + j];
    else if (r < 1280)  base = w_swiglu[j * 512 + (r - 768)];
    else                base = w_out[(r - 1280) * 64 + j];
    rv[j] = base;
    __syncthreads();

    float a = 0.f;
    #pragma unroll 8
    for (int k = 0; k < 64; k++) a += rv[k] * g_ao[k * 64 + j];
    nn[j] = silu_f(a);
    __syncthreads();

    float m = base;
    #pragma unroll 8
    for (int k = 0; k < 64; k++) m += nn[k] * out_w[j * 64 + k];

    if (r < 768)        out[O1 + r * 64 + j] = m;
    else if (r < 1280)  out[O2 + j * 512 + (r - 768)] = m;
    else                out[O3 + (r - 1280) * 64 + j] = m;

    float s = m, q = m * m;
    #pragma unroll
    for (int o = 16; o > 0; o >>= 1) {
        s += __shfl_down_sync(0xffffffff, s, o);
        q += __shfl_down_sync(0xffffffff, q, o);
    }
    __shared__ float t4[4];
    if ((j & 31) == 0) { t4[j >> 5] = s; t4[2 + (j >> 5)] = q; }
    __syncthreads();
    if (j == 0) g_rowstats[r] = make_float2(t4[0] + t4[1], t4[2] + t4[3]);
}

// =====================================================================
// Kernel D: per-matrix std (ddof=1) + gates -> g_scale[3]
//   one warp per matrix, shuffle-only reduction
// =====================================================================
__global__ __launch_bounds__(96)
void kD(const float* __restrict__ tao)
{
    const int w = threadIdx.x >> 5;
    const int l = threadIdx.x & 31;
    const int base = (w == 0) ? 0 : ((w == 1) ? 768 : 1280);
    const int cnt  = (w == 0) ? 768 : ((w == 1) ? 512 : 64);

    float s = 0.f, q = 0.f;
    for (int r = l; r < cnt; r += 32) {
        float2 v = g_rowstats[base + r];
        s += v.x; q += v.y;
    }
    #pragma unroll
    for (int o = 16; o > 0; o >>= 1) {
        s += __shfl_down_sync(0xffffffff, s, o);
        q += __shfl_down_sync(0xffffffff, q, o);
    }
    if (l == 0) {
        float n      = (w == 0) ? 49152.f : ((w == 1) ? 32768.f : 4096.f);
        float target = (w == 0) ? 0.125f : 0.0625f;
        float var = (q - s * s / n) / (n - 1.f);
        var = fmaxf(var, 0.f);
        float sd = sqrtf(var);
        float gv = fminf(fmaxf(fabsf(tao[w]), 1e-8f), 1.0f);
        g_scale[w] = target / (sd + 1e-8f) * gv;
    }
}

// =====================================================================
// Kernel E: scale weight outputs in place
// =====================================================================
__global__ __launch_bounds__(256)
void kE(float* __restrict__ out)
{
    int i = blockIdx.x * 256 + threadIdx.x;
    if (i < 86016) {
        int m = (i < 49152) ? 0 : ((i < 81920) ? 1 : 2);
        out[O1 + i] *= g_scale[m];
    }
}

// =====================================================================
extern "C" void kernel_launch(void* const* d_in, const int* in_sizes, int n_in,
                              void* d_out, int out_size)
{
    const float* x        = (const float*)d_in[0];
    const float* y        = (const float*)d_in[1];
    const float* w_qkv    = (const float*)d_in[2];
    const float* w_swiglu = (const float*)d_in[3];
    const float* w_out    = (const float*)d_in[4];
    const float* out_w    = (const float*)d_in[5];
    const float* tao      = (const float*)d_in[6];
    float* out = (float*)d_out;

    cudaFuncSetAttribute(kA, cudaFuncAttributeMaxDynamicSharedMemorySize, SMEM_BYTES);
    kA<<<512, 256, SMEM_BYTES>>>(x, y, w_swiglu, w_out, out);
    kB<<<64, 64>>>();
    kC<<<1344, 64>>>(w_qkv, w_swiglu, w_out, out_w, out);
    kD<<<1, 96>>>(tao);
    kE<<<336, 256>>>(out);
}

// round 6
// speedup vs baseline: 3.1198x; 1.1271x over previous
#include <cuda_runtime.h>
#include <cstdint>
#include <math.h>

// ---------------- output offsets ----------------
#define O1 4194304
#define O2 4243456
#define O3 4276224

// ---------------- smem layout (float indices) ----------------
#define SWO_OFF 0        // w_out tf32 [64][68]              (4352)
#define B0Y_OFF 4352     // y chunk buf0 [128][36]
#define B1Y_OFF 8960     // y chunk buf1 [128][36]
#define B0W_OFF 13568    // w chunk buf0 [128][36]
#define B1W_OFF 18176    // w chunk buf1 [128][36]
#define SU_OFF  4352     // phase2: u fp32 -> h tf32 [128][68]
#define SV_OFF  13056    // phase2: v fp32 [128][68]
#define SMEM_FLOATS 22784
#define SMEM_BYTES (SMEM_FLOATS * 4)

// ---------------- device scratch ----------------
__device__ float  g_aoPart[512 * 4096];
__device__ float  g_ao[4096];
__device__ float2 g_rowstats[1344];

__device__ __forceinline__ float silu_f(float v) {
    return __fdividef(v, 1.0f + __expf(-v));
}
__device__ __forceinline__ uint32_t f2tf32(float f) {
    uint32_t r; asm("cvt.rna.tf32.f32 %0, %1;" : "=r"(r) : "f"(f)); return r;
}
__device__ __forceinline__ float f2tf32f(float f) {
    return __uint_as_float(f2tf32(f));
}
__device__ __forceinline__ void mma_tf32(float c[4],
    uint32_t a0, uint32_t a1, uint32_t a2, uint32_t a3,
    uint32_t b0, uint32_t b1)
{
    asm volatile(
        "mma.sync.aligned.m16n8k8.row.col.f32.tf32.tf32.f32 "
        "{%0,%1,%2,%3},{%4,%5,%6,%7},{%8,%9},{%0,%1,%2,%3};"
        : "+f"(c[0]), "+f"(c[1]), "+f"(c[2]), "+f"(c[3])
        : "r"(a0), "r"(a1), "r"(a2), "r"(a3), "r"(b0), "r"(b1));
}

// =====================================================================
// Kernel A: 128-token tile per CTA; all matmuls via tf32 mma.sync.
//   GEMM1 pipelined over 8 k-chunks of 32, double-buffered; smem 89KB
//   -> 2 CTAs/SM for cross-CTA phase overlap.
//   Order: GEMM1 -> store u,v -> ao MMA -> h = u*silu(v) IN PLACE over
//   sU -> epilogue MMA -> y_out.
// =====================================================================
__global__ __launch_bounds__(256, 2)
void kA(const float* __restrict__ x, const float* __restrict__ y,
        const float* __restrict__ w_swiglu, const float* __restrict__ w_out,
        float* __restrict__ out)
{
    extern __shared__ float sm[];
    const int tid = threadIdx.x;
    const int lid = tid & 31;
    const int wid = tid >> 5;
    const int lg  = lid >> 2;       // 0..7
    const int lc  = lid & 3;        // 0..3
    const int wm  = wid & 1;        // 2 warps over M
    const int wn  = wid >> 1;       // 4 warps over N
    const int tok0 = blockIdx.x * 128;

    const float4* yf4 = reinterpret_cast<const float4*>(y);
    const float4* wf4 = reinterpret_cast<const float4*>(w_swiglu);

    // ---- load w_out -> sWO (tf32) [64][68] ----
    float* sWO = sm + SWO_OFF;
    #pragma unroll
    for (int r = 0; r < 4; r++) {
        int i = tid + r * 256;              // 0..1023
        int e = i >> 4, d4 = (i & 15) << 2;
        float4 wv = reinterpret_cast<const float4*>(w_out)[i];
        *reinterpret_cast<float4*>(&sWO[e * 68 + d4]) =
            make_float4(f2tf32f(wv.x), f2tf32f(wv.y), f2tf32f(wv.z), f2tf32f(wv.w));
    }

    // ================= GEMM1: uv = y @ w_swiglu^T, K=256 in 8 chunks of 32 =====
    float acc[4][4][4];
    #pragma unroll
    for (int a = 0; a < 4; a++)
        #pragma unroll
        for (int b = 0; b < 4; b++)
            #pragma unroll
            for (int k = 0; k < 4; k++) acc[a][b][k] = 0.f;

    float* const bufY[2] = { sm + B0Y_OFF, sm + B1Y_OFF };
    float* const bufW[2] = { sm + B0W_OFF, sm + B1W_OFF };

    const int ldrow = tid >> 3;             // 0..31
    const int ldc4  = tid & 7;              // float4 col within 32-chunk

    float4 ry[4], rw[4];

    // prefetch + store chunk 0
    #pragma unroll
    for (int r = 0; r < 4; r++) {
        int row = ldrow + r * 32;
        ry[r] = yf4[(size_t)(tok0 + row) * 64 + ldc4];
        rw[r] = wf4[(size_t)row * 64 + ldc4];
    }
    #pragma unroll
    for (int r = 0; r < 4; r++) {
        int row = ldrow + r * 32;
        *reinterpret_cast<float4*>(&bufY[0][row * 36 + ldc4 * 4]) =
            make_float4(f2tf32f(ry[r].x), f2tf32f(ry[r].y), f2tf32f(ry[r].z), f2tf32f(ry[r].w));
        *reinterpret_cast<float4*>(&bufW[0][row * 36 + ldc4 * 4]) =
            make_float4(f2tf32f(rw[r].x), f2tf32f(rw[r].y), f2tf32f(rw[r].z), f2tf32f(rw[r].w));
    }
    __syncthreads();

    #pragma unroll
    for (int c = 0; c < 8; c++) {
        // issue next chunk's global loads early
        if (c < 7) {
            #pragma unroll
            for (int r = 0; r < 4; r++) {
                int row = ldrow + r * 32;
                ry[r] = yf4[(size_t)(tok0 + row) * 64 + (c + 1) * 8 + ldc4];
                rw[r] = wf4[(size_t)row * 64 + (c + 1) * 8 + ldc4];
            }
        }

        // MMA over this chunk (4 k-steps of 8)
        const float* bY = bufY[c & 1];
        const float* bW = bufW[c & 1];
        #pragma unroll
        for (int ks = 0; ks < 4; ks++) {
            const int kk = ks * 8 + 2 * lc;
            uint32_t A[4][4];
            #pragma unroll
            for (int mt = 0; mt < 4; mt++) {
                const float* p = &bY[(wm * 64 + mt * 16 + lg) * 36 + kk];
                float2 a0 = *reinterpret_cast<const float2*>(p);
                float2 a1 = *reinterpret_cast<const float2*>(p + 8 * 36);
                A[mt][0] = __float_as_uint(a0.x); A[mt][2] = __float_as_uint(a0.y);
                A[mt][1] = __float_as_uint(a1.x); A[mt][3] = __float_as_uint(a1.y);
            }
            uint32_t B[4][2];
            #pragma unroll
            for (int nt = 0; nt < 4; nt++) {
                float2 bv = *reinterpret_cast<const float2*>(&bW[(wn * 32 + nt * 8 + lg) * 36 + kk]);
                B[nt][0] = __float_as_uint(bv.x); B[nt][1] = __float_as_uint(bv.y);
            }
            #pragma unroll
            for (int mt = 0; mt < 4; mt++)
                #pragma unroll
                for (int nt = 0; nt < 4; nt++)
                    mma_tf32(acc[mt][nt], A[mt][0], A[mt][1], A[mt][2], A[mt][3],
                             B[nt][0], B[nt][1]);
        }

        // store next chunk into the other buffer
        if (c < 7) {
            float* dY = bufY[(c + 1) & 1];
            float* dW = bufW[(c + 1) & 1];
            #pragma unroll
            for (int r = 0; r < 4; r++) {
                int row = ldrow + r * 32;
                *reinterpret_cast<float4*>(&dY[row * 36 + ldc4 * 4]) =
                    make_float4(f2tf32f(ry[r].x), f2tf32f(ry[r].y), f2tf32f(ry[r].z), f2tf32f(ry[r].w));
                *reinterpret_cast<float4*>(&dW[row * 36 + ldc4 * 4]) =
                    make_float4(f2tf32f(rw[r].x), f2tf32f(rw[r].y), f2tf32f(rw[r].z), f2tf32f(rw[r].w));
            }
        }
        __syncthreads();
    }

    // ---- store uv fragments -> sU (fp32), sV (fp32) ----
    float* sU = sm + SU_OFF;    // [128][68]
    float* sV = sm + SV_OFF;    // [128][68]
    {
        float* dst = (wn < 2) ? sU : sV;
        const int cbase = (wn & 1) * 32;
        #pragma unroll
        for (int mt = 0; mt < 4; mt++) {
            int row = wm * 64 + mt * 16 + lg;
            #pragma unroll
            for (int nt = 0; nt < 4; nt++) {
                int cb = cbase + nt * 8 + 2 * lc;
                *reinterpret_cast<float2*>(&dst[row * 68 + cb]) =
                    make_float2(acc[mt][nt][0], acc[mt][nt][1]);
                *reinterpret_cast<float2*>(&dst[(row + 8) * 68 + cb]) =
                    make_float2(acc[mt][nt][2], acc[mt][nt][3]);
            }
        }
    }

    // prefetch x fragments (hide LDG latency behind ao MMA)
    float2 xr[4][2][2];
    #pragma unroll
    for (int mt = 0; mt < 4; mt++)
        #pragma unroll
        for (int nt = 0; nt < 2; nt++) {
            int row = wm * 64 + mt * 16 + lg;
            int col = wn * 16 + nt * 8 + 2 * lc;
            xr[mt][nt][0] = *reinterpret_cast<const float2*>(&x[(size_t)(tok0 + row) * 64 + col]);
            xr[mt][nt][1] = *reinterpret_cast<const float2*>(&x[(size_t)(tok0 + row + 8) * 64 + col]);
        }
    __syncthreads();

    // ================= ao MMA: ao[d][e] = sum_t u[t][d] v[t][e] ================
    float acc3[2][2][4];
    #pragma unroll
    for (int a = 0; a < 2; a++)
        #pragma unroll
        for (int b = 0; b < 2; b++)
            #pragma unroll
            for (int k = 0; k < 4; k++) acc3[a][b][k] = 0.f;

    #pragma unroll
    for (int ks = 0; ks < 16; ks++) {
        const int kk = ks * 8;
        const int t0 = kk + 2 * lc;
        const int t1 = kk + 2 * lc + 1;
        uint32_t A[2][4];
        #pragma unroll
        for (int mt = 0; mt < 2; mt++) {
            int rb = wm * 32 + mt * 16;
            A[mt][0] = f2tf32(sU[t0 * 68 + rb + lg]);
            A[mt][1] = f2tf32(sU[t0 * 68 + rb + lg + 8]);
            A[mt][2] = f2tf32(sU[t1 * 68 + rb + lg]);
            A[mt][3] = f2tf32(sU[t1 * 68 + rb + lg + 8]);
        }
        uint32_t B[2][2];
        #pragma unroll
        for (int nt = 0; nt < 2; nt++) {
            int nb = wn * 16 + nt * 8;
            B[nt][0] = f2tf32(sV[t0 * 68 + nb + lg]);
            B[nt][1] = f2tf32(sV[t1 * 68 + nb + lg]);
        }
        #pragma unroll
        for (int mt = 0; mt < 2; mt++)
            #pragma unroll
            for (int nt = 0; nt < 2; nt++)
                mma_tf32(acc3[mt][nt], A[mt][0], A[mt][1], A[mt][2], A[mt][3],
                         B[nt][0], B[nt][1]);
    }

    // write ao partials
    {
        float* dst = g_aoPart + (size_t)blockIdx.x * 4096;
        #pragma unroll
        for (int mt = 0; mt < 2; mt++)
            #pragma unroll
            for (int nt = 0; nt < 2; nt++) {
                int row = wm * 32 + mt * 16 + lg;
                int col = wn * 16 + nt * 8 + 2 * lc;
                *reinterpret_cast<float2*>(&dst[row * 64 + col]) =
                    make_float2(acc3[mt][nt][0], acc3[mt][nt][1]);
                *reinterpret_cast<float2*>(&dst[(row + 8) * 64 + col]) =
                    make_float2(acc3[mt][nt][2], acc3[mt][nt][3]);
            }
    }
    __syncthreads();    // all ao reads of sU/sV done

    // ---- h = u * silu(v) IN PLACE over sU (tf32) ----
    #pragma unroll
    for (int r = 0; r < 8; r++) {
        int i = tid + r * 256;              // 0..2047 float4s
        int t = i >> 4, d4 = (i & 15) << 2;
        float4 u4 = *reinterpret_cast<const float4*>(&sU[t * 68 + d4]);
        float4 v4 = *reinterpret_cast<const float4*>(&sV[t * 68 + d4]);
        *reinterpret_cast<float4*>(&sU[t * 68 + d4]) = make_float4(
            f2tf32f(u4.x * silu_f(v4.x)), f2tf32f(u4.y * silu_f(v4.y)),
            f2tf32f(u4.z * silu_f(v4.z)), f2tf32f(u4.w * silu_f(v4.w)));
    }
    __syncthreads();

    // ================= Epilogue MMA: y_part = h @ w_out^T ======================
    float acc2[4][2][4];
    #pragma unroll
    for (int a = 0; a < 4; a++)
        #pragma unroll
        for (int b = 0; b < 2; b++)
            #pragma unroll
            for (int k = 0; k < 4; k++) acc2[a][b][k] = 0.f;

    const float* sH = sU;
    #pragma unroll
    for (int ks = 0; ks < 8; ks++) {
        const int kk = ks * 8 + 2 * lc;
        uint32_t A[4][4];
        #pragma unroll
        for (int mt = 0; mt < 4; mt++) {
            const float* p = &sH[(wm * 64 + mt * 16 + lg) * 68 + kk];
            float2 a0 = *reinterpret_cast<const float2*>(p);
            float2 a1 = *reinterpret_cast<const float2*>(p + 8 * 68);
            A[mt][0] = __float_as_uint(a0.x); A[mt][2] = __float_as_uint(a0.y);
            A[mt][1] = __float_as_uint(a1.x); A[mt][3] = __float_as_uint(a1.y);
        }
        uint32_t B[2][2];
        #pragma unroll
        for (int nt = 0; nt < 2; nt++) {
            float2 bv = *reinterpret_cast<const float2*>(&sWO[(wn * 16 + nt * 8 + lg) * 68 + kk]);
            B[nt][0] = __float_as_uint(bv.x); B[nt][1] = __float_as_uint(bv.y);
        }
        #pragma unroll
        for (int mt = 0; mt < 4; mt++)
            #pragma unroll
            for (int nt = 0; nt < 2; nt++)
                mma_tf32(acc2[mt][nt], A[mt][0], A[mt][1], A[mt][2], A[mt][3],
                         B[nt][0], B[nt][1]);
    }

    // write y_out = x + y_part
    #pragma unroll
    for (int mt = 0; mt < 4; mt++) {
        #pragma unroll
        for (int nt = 0; nt < 2; nt++) {
            int row = wm * 64 + mt * 16 + lg;
            int col = wn * 16 + nt * 8 + 2 * lc;
            size_t o0 = (size_t)(tok0 + row) * 64 + col;
            size_t o1 = (size_t)(tok0 + row + 8) * 64 + col;
            *reinterpret_cast<float2*>(&out[o0]) =
                make_float2(xr[mt][nt][0].x + acc2[mt][nt][0], xr[mt][nt][0].y + acc2[mt][nt][1]);
            *reinterpret_cast<float2*>(&out[o1]) =
                make_float2(xr[mt][nt][1].x + acc2[mt][nt][2], xr[mt][nt][1].y + acc2[mt][nt][3]);
        }
    }
}

// =====================================================================
// Kernel B: reduce ao partials, /64, per-row rms-norm
// =====================================================================
__global__ __launch_bounds__(64)
void kB()
{
    const int d = blockIdx.x;
    const int e = threadIdx.x;
    float s = 0.f;
    const float* p = &g_aoPart[d * 64 + e];
    #pragma unroll 16
    for (int b = 0; b < 512; b++) s += p[(size_t)b * 4096];
    s *= (1.0f / 64.0f);

    float q = s * s;
    #pragma unroll
    for (int o = 16; o > 0; o >>= 1) q += __shfl_down_sync(0xffffffff, q, o);
    __shared__ float tmp[2];
    if ((e & 31) == 0) tmp[e >> 5] = q;
    __syncthreads();
    float ms = (tmp[0] + tmp[1]) * (1.0f / 64.0f) + 1.1920929e-07f;
    g_ao[d * 64 + e] = s * rsqrtf(ms);
}

// =====================================================================
// Kernel C: weight updates (unnormalized) + per-row stats
// =====================================================================
__global__ __launch_bounds__(64)
void kC(const float* __restrict__ w_qkv, const float* __restrict__ w_swiglu,
        const float* __restrict__ w_out, const float* __restrict__ out_w,
        float* __restrict__ out)
{
    const int r = blockIdx.x;
    const int j = threadIdx.x;
    __shared__ float rv[64], nn[64];

    float base;
    if (r < 768)        base = w_qkv[r * 64 + j];
    else if (r < 1280)  base = w_swiglu[j * 512 + (r - 768)];
    else                base = w_out[(r - 1280) * 64 + j];
    rv[j] = base;
    __syncthreads();

    float a = 0.f;
    #pragma unroll 8
    for (int k = 0; k < 64; k++) a += rv[k] * g_ao[k * 64 + j];
    nn[j] = silu_f(a);
    __syncthreads();

    float m = base;
    #pragma unroll 8
    for (int k = 0; k < 64; k++) m += nn[k] * out_w[j * 64 + k];

    if (r < 768)        out[O1 + r * 64 + j] = m;
    else if (r < 1280)  out[O2 + j * 512 + (r - 768)] = m;
    else                out[O3 + (r - 1280) * 64 + j] = m;

    float s = m, q = m * m;
    #pragma unroll
    for (int o = 16; o > 0; o >>= 1) {
        s += __shfl_down_sync(0xffffffff, s, o);
        q += __shfl_down_sync(0xffffffff, q, o);
    }
    __shared__ float t4[4];
    if ((j & 31) == 0) { t4[j >> 5] = s; t4[2 + (j >> 5)] = q; }
    __syncthreads();
    if (j == 0) g_rowstats[r] = make_float2(t4[0] + t4[1], t4[2] + t4[3]);
}

// =====================================================================
// Kernel DE: each block computes its matrix's scale from rowstats
// (redundantly; <=768 values, one per thread) then scales its 1024
// output elements. Grid 84 x 1024 == 86016 elements exactly; matrix
// boundaries are block-aligned (48 / 32 / 4 blocks).
// =====================================================================
__global__ __launch_bounds__(1024)
void kDE(const float* __restrict__ tao, float* __restrict__ out)
{
    const int b = blockIdx.x;
    const int tid = threadIdx.x;
    const int m = (b < 48) ? 0 : ((b < 80) ? 1 : 2);
    const int base = (m == 0) ? 0 : ((m == 1) ? 768 : 1280);
    const int cnt  = (m == 0) ? 768 : ((m == 1) ? 512 : 64);

    float s = 0.f, q = 0.f;
    if (tid < cnt) { float2 v = g_rowstats[base + tid]; s = v.x; q = v.y; }
    #pragma unroll
    for (int o = 16; o > 0; o >>= 1) {
        s += __shfl_down_sync(0xffffffff, s, o);
        q += __shfl_down_sync(0xffffffff, q, o);
    }
    __shared__ float ws[32], wq[32];
    if ((tid & 31) == 0) { ws[tid >> 5] = s; wq[tid >> 5] = q; }
    __syncthreads();
    __shared__ float sc;
    if (tid == 0) {
        float S = 0.f, Q = 0.f;
        #pragma unroll
        for (int i = 0; i < 32; i++) { S += ws[i]; Q += wq[i]; }
        float n      = (m == 0) ? 49152.f : ((m == 1) ? 32768.f : 4096.f);
        float target = (m == 0) ? 0.125f : 0.0625f;
        float var = (Q - S * S / n) / (n - 1.f);
        var = fmaxf(var, 0.f);
        float sd = sqrtf(var);
        float gv = fminf(fmaxf(fabsf(tao[m]), 1e-8f), 1.0f);
        sc = target / (sd + 1e-8f) * gv;
    }
    __syncthreads();
    int i = b * 1024 + tid;
    out[O1 + i] *= sc;
}

// =====================================================================
extern "C" void kernel_launch(void* const* d_in, const int* in_sizes, int n_in,
                              void* d_out, int out_size)
{
    const float* x        = (const float*)d_in[0];
    const float* y        = (const float*)d_in[1];
    const float* w_qkv    = (const float*)d_in[2];
    const float* w_swiglu = (const float*)d_in[3];
    const float* w_out    = (const float*)d_in[4];
    const float* out_w    = (const float*)d_in[5];
    const float* tao      = (const float*)d_in[6];
    float* out = (float*)d_out;

    cudaFuncSetAttribute(kA, cudaFuncAttributeMaxDynamicSharedMemorySize, SMEM_BYTES);
    kA<<<512, 256, SMEM_BYTES>>>(x, y, w_swiglu, w_out, out);
    kB<<<64, 64>>>();
    kC<<<1344, 64>>>(w_qkv, w_swiglu, w_out, out_w, out);
    kDE<<<84, 1024>>>(tao, out);
}